// round 9
// baseline (speedup 1.0000x reference)
#include <cuda_runtime.h>
#include <cuda_bf16.h>

// Quanvolutional layer: light-cone-pruned circuits + packed f32x2 math
// (two batch-images per thread in the two f32x2 lanes).
// inputs:  (16, 3, 32, 32) float32
// weights: (16, 3, 16)     float32
// output:  (16, 16, 31, 31) float32  [B, O, Hp, Wp]

#define HP 31
#define WP 31
#define NPOS2 (8 * HP * WP)      // 7688 thread-positions (b in 0..7, pairs with b+8)
#define NPIX (16 * 3 * 32 * 32)  // 49152 input pixels

typedef unsigned long long u64;  // packed f32x2: lane0 = batch b, lane1 = batch b+8

__device__ float2 g_wtrig[16 * 3 * 16];   // (cos, sin) of half weight angles
__device__ float2 g_ptrig[NPIX];          // per-pixel (cos(x/2), sin(x/2))

// Heavy circuits first so the tail wave is made of cheap blocks.
__constant__ int c_omap[16] = {3, 8, 13, 4, 9, 14, 2, 7, 12, 0, 5, 10, 15, 1, 6, 11};

__global__ __launch_bounds__(128) void trig_kernel(const float* __restrict__ w,
                                                   const float* __restrict__ in) {
    int idx = blockIdx.x * blockDim.x + threadIdx.x;  // 0..12287
    if (idx < 16 * 3 * 16) {
        float sn, cs;
        sincosf(0.5f * w[idx], &sn, &cs);
        g_wtrig[idx] = make_float2(cs, sn);
    }
    float4 x = reinterpret_cast<const float4*>(in)[idx];
    float4 lo, hi;
    __sincosf(0.5f * x.x, &lo.y, &lo.x);
    __sincosf(0.5f * x.y, &lo.w, &lo.z);
    __sincosf(0.5f * x.z, &hi.y, &hi.x);
    __sincosf(0.5f * x.w, &hi.w, &hi.z);
    float4* outp = reinterpret_cast<float4*>(g_ptrig) + 2 * idx;
    outp[0] = lo;
    outp[1] = hi;
}

// ---- packed f32x2 primitives (sm_100+; SASS FFMA2/FMUL2 — PTX-only path) ----
__device__ __forceinline__ u64 pk2(float lo, float hi) {
    u64 r; asm("mov.b64 %0, {%1,%2};" : "=l"(r) : "f"(lo), "f"(hi)); return r;
}
__device__ __forceinline__ u64 rep2(float x) { return pk2(x, x); }
__device__ __forceinline__ float2 unpk2(u64 v) {
    float2 r; asm("mov.b64 {%0,%1}, %2;" : "=f"(r.x), "=f"(r.y) : "l"(v)); return r;
}
__device__ __forceinline__ u64 mul2_(u64 a, u64 b) {
    u64 r; asm("mul.rn.f32x2 %0,%1,%2;" : "=l"(r) : "l"(a), "l"(b)); return r;
}
__device__ __forceinline__ u64 fma2_(u64 a, u64 b, u64 c) {
    u64 r; asm("fma.rn.f32x2 %0,%1,%2,%3;" : "=l"(r) : "l"(a), "l"(b), "l"(c)); return r;
}

// RY on wire W, packed. cs/sn/nsn are lane-replicated weight trig (nsn = -sn).
template <int W>
__device__ __forceinline__ void ry2(u64 s[16], u64 cs, u64 sn, u64 nsn) {
    constexpr int bit = 8 >> W;
#pragma unroll
    for (int i = 0; i < 16; i++) {
        if ((i & bit) == 0) {
            u64 a = s[i], b = s[i | bit];
            s[i]       = fma2_(b, nsn, mul2_(a, cs));
            s[i | bit] = fma2_(b, cs,  mul2_(a, sn));
        }
    }
}
template <int W>
__device__ __forceinline__ void ryw2(u64 s[16], float2 w) {
    ry2<W>(s, rep2(w.x), rep2(w.y), rep2(-w.y));
}

// CNOT: compile-time 64-bit register permutation.
template <int C, int T>
__device__ __forceinline__ void cx2(u64 s[16]) {
    constexpr int cb = 8 >> C, tb = 8 >> T;
#pragma unroll
    for (int i = 0; i < 16; i++) {
        if ((i & cb) && !(i & tb)) {
            u64 tmp = s[i]; s[i] = s[i | tb]; s[i | tb] = tmp;
        }
    }
}

// Fuse weight half-angle into packed pixel trig (angle addition).
__device__ __forceinline__ void fuse2(u64& cx_, u64& sx_, float2 w) {
    u64 cw = rep2(w.x), sw = rep2(w.y), nsw = rep2(-w.y);
    u64 nc = fma2_(sx_, nsw, mul2_(cx_, cw));
    u64 ns = fma2_(cx_, sw,  mul2_(sx_, cw));
    cx_ = nc; sx_ = ns;
}

// Product state from 4 packed wire (cos,sin) pairs.
__device__ __forceinline__ void embed2(u64 s[16], u64 c0, u64 s0, u64 c1, u64 s1,
                                       u64 c2, u64 s2, u64 c3, u64 s3) {
    u64 p01[4] = { mul2_(c0, c1), mul2_(c0, s1), mul2_(s0, c1), mul2_(s0, s1) };
    u64 p23[4] = { mul2_(c2, c3), mul2_(c2, s3), mul2_(s2, c3), mul2_(s2, s3) };
#pragma unroll
    for (int q = 0; q < 16; q++) s[q] = mul2_(p01[q >> 2], p23[q & 3]);
}

// Accumulate sum of squares into accP (wire0=0) / accN (wire0=1), per lane.
__device__ __forceinline__ void expz2(const u64 s[16], u64& accP, u64& accN) {
#pragma unroll
    for (int q = 0; q < 16; q++) {
        if (q & 8) accN = fma2_(s[q], s[q], accN);
        else       accP = fma2_(s[q], s[q], accP);
    }
}

__global__ __launch_bounds__(128, 4) void quanv_kernel(float* __restrict__ out) {
    const int o = c_omap[blockIdx.y];
    __shared__ float2 wcs[3][16];
    if (threadIdx.x < 48) {
        int c = threadIdx.x >> 4, j = threadIdx.x & 15;
        wcs[c][j] = g_wtrig[o * 48 + threadIdx.x];
    }
    __syncthreads();

    int p = blockIdx.x * blockDim.x + threadIdx.x;
    if (p >= NPOS2) return;
    int b  = p / (HP * WP);           // 0..7; lane1 handles b+8
    int hw = p - b * (HP * WP);
    int h  = hw / WP;
    int w  = hw - h * WP;

    const int circ = o % 5;
    u64 accP = 0ull, accN = 0ull;     // bit pattern 0 == (0.0f, 0.0f)

#pragma unroll 1
    for (int c = 0; c < 3; c++) {
        const float2* tpA = g_ptrig + (((b * 3 + c) * 32) + h) * 32 + w;
        const float2* tpB = tpA + 8 * 3 * 32 * 32;  // batch b+8
        float2 A0 = tpA[0],  B0 = tpB[0];
        float2 A1 = tpA[1],  B1 = tpB[1];
        float2 A2 = tpA[32], B2 = tpB[32];
        float2 A3 = tpA[33], B3 = tpB[33];
        u64 c0 = pk2(A0.x, B0.x), s0 = pk2(A0.y, B0.y);
        u64 c1 = pk2(A1.x, B1.x), s1 = pk2(A1.y, B1.y);
        u64 c2 = pk2(A2.x, B2.x), s2 = pk2(A2.y, B2.y);
        u64 c3 = pk2(A3.x, B3.x), s3 = pk2(A3.y, B3.y);
        const float2* W = wcs[c];

        switch (circ) {
            case 0: {  // ran -> wires {0,1}: fused ry0,ry1; cx01; ry0(w4)
                fuse2(c0, s0, W[0]);
                fuse2(c1, s1, W[1]);
                u64 t00 = mul2_(c0, c1), t01 = mul2_(c0, s1);
                u64 t10 = mul2_(s0, s1), t11 = mul2_(s0, c1);
                u64 c4 = rep2(W[4].x), s4v = rep2(W[4].y), n4 = rep2(-W[4].y);
                u64 n00 = fma2_(t10, n4, mul2_(t00, c4));
                u64 n10 = fma2_(t10, c4, mul2_(t00, s4v));
                u64 n01 = fma2_(t11, n4, mul2_(t01, c4));
                u64 n11 = fma2_(t11, c4, mul2_(t01, s4v));
                accP = fma2_(n00, n00, fma2_(n01, n01, accP));
                accN = fma2_(n10, n10, fma2_(n11, n11, accN));
                break;
            }
            case 1: {  // line -> single qubit: <Z0> = cos(x0 + w0)
                fuse2(c0, s0, W[0]);
                accP = fma2_(c0, c0, accP);
                accN = fma2_(s0, s0, accN);
                break;
            }
            case 2: {  // ring -> fused embed, 4 CNOTs, ry0(w4)
                fuse2(c0, s0, W[0]); fuse2(c1, s1, W[1]);
                fuse2(c2, s2, W[2]); fuse2(c3, s3, W[3]);
                u64 s[16];
                embed2(s, c0, s0, c1, s1, c2, s2, c3, s3);
                cx2<0, 1>(s); cx2<1, 2>(s); cx2<2, 3>(s); cx2<3, 0>(s);
                ryw2<0>(s, W[4]);
                expz2(s, accP, accN);
                break;
            }
            case 3: {  // doublering -> fused embed; 10 RYs; pruned tail
                fuse2(c0, s0, W[0]); fuse2(c1, s1, W[1]);
                fuse2(c2, s2, W[2]); fuse2(c3, s3, W[3]);
                u64 s[16];
                embed2(s, c0, s0, c1, s1, c2, s2, c3, s3);
                cx2<0, 1>(s); cx2<1, 2>(s); cx2<2, 3>(s); cx2<3, 0>(s);
                ryw2<0>(s, W[4]); ryw2<1>(s, W[5]);
                ryw2<2>(s, W[6]); ryw2<3>(s, W[7]);
                cx2<3, 0>(s); cx2<2, 3>(s); cx2<1, 2>(s); cx2<0, 1>(s);
                ryw2<0>(s, W[8]);  ryw2<1>(s, W[9]);
                ryw2<2>(s, W[10]); ryw2<3>(s, W[11]);
                cx2<0, 1>(s); cx2<1, 2>(s); cx2<2, 3>(s); cx2<3, 0>(s);
                ryw2<0>(s, W[12]);   // ry1(w13), ry2(w14) pruned
                ryw2<3>(s, W[15]);
                cx2<3, 0>(s);        // trailing cx23,cx12,cx01 pruned
                expz2(s, accP, accN);
                break;
            }
            default: {  // blockring -> fused embed; 8 RYs
                fuse2(c0, s0, W[0]); fuse2(c1, s1, W[1]);
                fuse2(c2, s2, W[2]); fuse2(c3, s3, W[3]);
                u64 s[16];
                embed2(s, c0, s0, c1, s1, c2, s2, c3, s3);
                cx2<0, 1>(s); cx2<2, 3>(s); cx2<1, 2>(s); cx2<3, 0>(s);
                ryw2<0>(s, W[4]); ryw2<1>(s, W[5]);
                ryw2<2>(s, W[6]); ryw2<3>(s, W[7]);
                cx2<0, 1>(s); cx2<2, 3>(s); cx2<1, 2>(s); cx2<3, 0>(s);
                ryw2<0>(s, W[8]);  ryw2<1>(s, W[9]);
                ryw2<2>(s, W[10]); ryw2<3>(s, W[11]);
                cx2<0, 1>(s); cx2<2, 3>(s); cx2<1, 2>(s); cx2<3, 0>(s);
                expz2(s, accP, accN);
                break;
            }
        }
    }

    float2 P = unpk2(accP), N = unpk2(accN);
    int idxA = ((b * 16 + o) * HP + h) * WP + w;
    out[idxA] = P.x - N.x;
    out[idxA + 8 * 16 * HP * WP] = P.y - N.y;   // batch b+8
}

extern "C" void kernel_launch(void* const* d_in, const int* in_sizes, int n_in,
                              void* d_out, int out_size) {
    const float* in = (const float*)d_in[0];   // (16,3,32,32)
    const float* w  = (const float*)d_in[1];   // (16,3,16)
    float* out = (float*)d_out;                // (16,16,31,31)

    trig_kernel<<<96, 128>>>(w, in);           // 12288 threads = NPIX/4

    dim3 grid((NPOS2 + 127) / 128, 16);        // 61 x 16 blocks
    quanv_kernel<<<grid, 128>>>(out);
}